// round 16
// baseline (speedup 1.0000x reference)
#include <cuda_runtime.h>
#include <cuda_bf16.h>
#include <cstdint>

#define TSTEPS 2048
#define BATCH  32
#define IDIM   512
#define HDIM   512
#define GDIM   2048   // 4*H

#define RG2     256    // recurrence CTAs (2 per SM, cross-group pairs)
#define CARRV   64     // arrivals per counter per step: 32 CTAs * 2 cell warps
#define SLABW   260    // slab b-row stride in words
#define NBAR    (1 + TSTEPS)

#define P1T     4      // timesteps per p1 CTA (N = 32*P1T = 128)

#define TOTX (TSTEPS * BATCH * IDIM)
#define TOTW (GDIM * IDIM)

// ---- static device scratch ----
__device__ float g_xpre[(size_t)TSTEPS * GDIM * BATCH];     // [t][g][b]
__device__ unsigned g_hhi[2][BATCH * 256];                  // h hi plane [b][kpair]
__device__ unsigned g_hlo[2][BATCH * 256];                  // h lo plane
// counters: (bb, half) -> own 128B line
__device__ __align__(128) unsigned long long g_cnt8[4 * 2 * 16];
__device__ uint4 g_xhi4[TOTX / 8], g_xlo4[TOTX / 8];
__device__ uint4 g_whi4[TOTW / 8], g_wlo4[TOTW / 8];

// ---- helpers ----
__device__ __forceinline__ void mma_bf16(float (&d)[4], const unsigned (&a)[4],
                                         unsigned b0, unsigned b1)
{
    asm("mma.sync.aligned.m16n8k16.row.col.f32.bf16.bf16.f32 "
        "{%0,%1,%2,%3}, {%4,%5,%6,%7}, {%8,%9}, {%0,%1,%2,%3};"
        : "+f"(d[0]), "+f"(d[1]), "+f"(d[2]), "+f"(d[3])
        : "r"(a[0]), "r"(a[1]), "r"(a[2]), "r"(a[3]), "r"(b0), "r"(b1));
}
__device__ __forceinline__ void cpasync16(uint32_t s, const void* g)
{
    asm volatile("cp.async.cg.shared.global [%0], [%1], 16;"
                 :: "r"(s), "l"(g) : "memory");
}
__device__ __forceinline__ void bsplit(float f0, float f1,
                                       unsigned& hp, unsigned& lp)
{
    asm("cvt.rn.bf16x2.f32 %0, %1, %2;" : "=r"(hp) : "f"(f1), "f"(f0));
    float h0 = __uint_as_float(hp << 16);
    float h1 = __uint_as_float(hp & 0xFFFF0000u);
    float r0 = f0 - h0, r1 = f1 - h1;
    asm("cvt.rn.bf16x2.f32 %0, %1, %2;" : "=r"(lp) : "f"(r1), "f"(r0));
}
__device__ __forceinline__ float fsig(float x)
{
    return __fdividef(1.f, 1.f + __expf(-x));
}
__device__ __forceinline__ float ftanh(float x)
{
    float ax = fabsf(x);
    float e  = __expf(-2.f * ax);
    float t  = __fdividef(1.f - e, 1.f + e);
    return copysignf(t, x);
}
__device__ __forceinline__ void gbar_arrive(unsigned long long* p)
{
    asm volatile("red.release.gpu.add.u64 [%0], %1;"
                 :: "l"(p), "l"(1ULL) : "memory");
}
__device__ __forceinline__ void gbar_spin(unsigned long long* p,
                                          unsigned long long target)
{
    unsigned long long v;
    do {
        asm volatile("ld.acquire.gpu.b64 %0, [%1];"
                     : "=l"(v) : "l"(p) : "memory");
    } while (v < target);
}

// ============================================================
// Prep: split fp32 -> bf16 hi/lo planes (x, Wi)
// ============================================================
__global__ void __launch_bounds__(256) split_x(const float* __restrict__ x)
{
    int i = blockIdx.x * 256 + threadIdx.x;
    __nv_bfloat16* hp = (__nv_bfloat16*)g_xhi4;
    __nv_bfloat16* lp = (__nv_bfloat16*)g_xlo4;
    float v = x[i];
    __nv_bfloat16 h = __float2bfloat16(v);
    hp[i] = h;
    lp[i] = __float2bfloat16(v - __bfloat162float(h));
}
__global__ void __launch_bounds__(256) split_wi(const float* __restrict__ W)
{
    int i = blockIdx.x * 256 + threadIdx.x;
    __nv_bfloat16* hp = (__nv_bfloat16*)g_whi4;
    __nv_bfloat16* lp = (__nv_bfloat16*)g_wlo4;
    float v = W[i];
    __nv_bfloat16 h = __float2bfloat16(v);
    hp[i] = h;
    lp[i] = __float2bfloat16(v - __bfloat162float(h));
}

// ============================================================
// Phase 1: 128 g x 128 n, cp.async staging, 2 CTAs/SM — R14 version
// ============================================================
extern __shared__ __align__(16) unsigned dynsm[];

__global__ void __launch_bounds__(256, 2) p1_gemm(
    const float* __restrict__ bi, const float* __restrict__ bh)
{
    unsigned* sw0 = dynsm;
    unsigned* sw1 = dynsm + 128 * 36;
    unsigned* sx0 = dynsm + 2 * 128 * 36;
    unsigned* sx1 = dynsm + 3 * 128 * 36;

    const int t0    = blockIdx.y * P1T;
    const int gbase = blockIdx.x * 128;
    const int tid   = threadIdx.x;
    const int wid   = tid >> 5;
    const int lane  = tid & 31;
    const int g     = lane >> 2;
    const int t4    = lane & 3;

    uint32_t wdst0[4], wdst1[4], xdst0[4], xdst1[4];
    size_t   wbase[4], xbase[4];
    {
        uint32_t b0 = (uint32_t)__cvta_generic_to_shared(sw0);
        uint32_t b1 = (uint32_t)__cvta_generic_to_shared(sw1);
        uint32_t b2 = (uint32_t)__cvta_generic_to_shared(sx0);
        uint32_t b3 = (uint32_t)__cvta_generic_to_shared(sx1);
        #pragma unroll
        for (int r = 0; r < 4; r++) {
            int ch  = r * 256 + tid;
            int row = ch >> 3, c8 = ch & 7;
            uint32_t doff = (uint32_t)(row * 9 + c8) * 16u;
            wdst0[r] = b0 + doff;  wdst1[r] = b1 + doff;
            xdst0[r] = b2 + doff;  xdst1[r] = b3 + doff;
            wbase[r] = (size_t)(gbase + row) * 64 + c8;
            int tl = row >> 5, b = row & 31;
            xbase[r] = ((size_t)(t0 + tl) * BATCH + b) * 64 + c8;
        }
    }

    float acc[16][4];
    #pragma unroll
    for (int nt = 0; nt < 16; nt++)
        #pragma unroll
        for (int i = 0; i < 4; i++) acc[nt][i] = 0.f;

    for (int kb = 0; kb < IDIM; kb += 64) {
        const int k8 = kb >> 3;
        __syncthreads();
        #pragma unroll
        for (int r = 0; r < 4; r++) {
            cpasync16(wdst0[r], g_whi4 + wbase[r] + k8);
            cpasync16(wdst1[r], g_wlo4 + wbase[r] + k8);
            cpasync16(xdst0[r], g_xhi4 + xbase[r] + k8);
            cpasync16(xdst1[r], g_xlo4 + xbase[r] + k8);
        }
        asm volatile("cp.async.commit_group;");
        asm volatile("cp.async.wait_group 0;" ::: "memory");
        __syncthreads();

        #pragma unroll
        for (int c = 0; c < 4; c++) {
            const int aw = (wid * 16 + g) * 36 + c * 8 + t4;
            unsigned ahi[4], alo[4];
            ahi[0] = sw0[aw];            ahi[1] = sw0[aw + 8 * 36];
            ahi[2] = sw0[aw + 4];        ahi[3] = sw0[aw + 8 * 36 + 4];
            alo[0] = sw1[aw];            alo[1] = sw1[aw + 8 * 36];
            alo[2] = sw1[aw + 4];        alo[3] = sw1[aw + 8 * 36 + 4];
            #pragma unroll
            for (int nt = 0; nt < 16; nt++) {
                const int bw = (nt * 8 + g) * 36 + c * 8 + t4;
                unsigned bh0 = sx0[bw], bh1 = sx0[bw + 4];
                unsigned bl0 = sx1[bw], bl1 = sx1[bw + 4];
                mma_bf16(acc[nt], ahi, bh0, bh1);
                mma_bf16(acc[nt], alo, bh0, bh1);
                mma_bf16(acc[nt], ahi, bl0, bl1);
            }
        }
    }

    const int grow0 = gbase + wid * 16 + g;
    const int grow1 = grow0 + 8;
    const float bb0 = __ldg(bi + grow0) + __ldg(bh + grow0);
    const float bb1 = __ldg(bi + grow1) + __ldg(bh + grow1);
    #pragma unroll
    for (int nt = 0; nt < 16; nt++) {
        int tl = nt >> 2;
        int b  = (nt & 3) * 8 + 2 * t4;
        float* op = g_xpre + (size_t)(t0 + tl) * GDIM * BATCH;
        *(float2*)(op + (size_t)grow0 * BATCH + b) =
            make_float2(acc[nt][0] + bb0, acc[nt][1] + bb0);
        *(float2*)(op + (size_t)grow1 * BATCH + b) =
            make_float2(acc[nt][2] + bb1, acc[nt][3] + bb1);
    }
}

// ============================================================
// Phase 2 v4: CTA = 8 j x 8 b, 128 threads, 4 warps; 2 CTAs/SM.
// bid>=128 shifts bb by +1 so co-resident pairs (i, i+148) come
// from DIFFERENT (independent) bb groups -> drift hides handoff.
// warp w: mtp = w&1 (gate pair), kh = w>>1 (k-half).
// m16 A-rows = [gate 2mtp, j 0-7][gate 2mtp+1, j 0-7].
// ============================================================
__global__ void __launch_bounds__(128, 2) lstm_rec(
    const float* __restrict__ Wh, float* __restrict__ out)
{
    __shared__ __align__(16) unsigned slabH[8][SLABW];  // [b][kpair]
    __shared__ __align__(16) unsigned slabL[8][SLABW];
    __shared__ float sred[2][2][2][16][10];             // [parity][mtp][kh][row][b]

    const int tid  = threadIdx.x;
    const int bid  = blockIdx.x;
    // cross-group pairing remap
    const int jb   = (bid < 128) ? (bid >> 2) : (32 + ((bid - 128) >> 2));
    const int bb   = (bid < 128) ? (bid & 3) : (((bid & 3) + 1) & 3);
    const int j0   = jb * 8;
    const int b0   = bb * 8;
    const int lane = tid & 31;
    const int gid  = lane >> 2;
    const int t4   = lane & 3;
    const int warp = tid >> 5;
    const int mtp  = warp & 1;             // gate pair {2mtp, 2mtp+1}
    const int kh   = warp >> 1;            // k-half

    const int half = jb >> 5;              // which k-half this CTA produces
    unsigned long long* acnt = &g_cnt8[(bb * 2 + half) * 16];  // arrive
    unsigned long long* scnt = &g_cnt8[(bb * 2 + kh) * 16];    // spin

    unsigned long long v0;
    asm volatile("ld.acquire.gpu.b64 %0, [%1];" : "=l"(v0) : "l"(scnt) : "memory");
    const unsigned long long per  = (unsigned long long)NBAR * CARRV;
    const unsigned long long base = (v0 / per) * per;

    // ---- preload Wh fragments: rows (gate 2mtp, j gid) & (gate 2mtp+1, j gid)
    unsigned ahi[16][4], alo[16][4];
    {
        const int r0 = (2 * mtp) * HDIM + j0 + gid;
        const int r1 = (2 * mtp + 1) * HDIM + j0 + gid;
        #pragma unroll
        for (int c = 0; c < 16; c++) {
            int kb = kh * 256 + c * 16 + 2 * t4;
            float a00 = Wh[(size_t)r0 * HDIM + kb];
            float a01 = Wh[(size_t)r0 * HDIM + kb + 1];
            float a10 = Wh[(size_t)r1 * HDIM + kb];
            float a11 = Wh[(size_t)r1 * HDIM + kb + 1];
            float a20 = Wh[(size_t)r0 * HDIM + kb + 8];
            float a21 = Wh[(size_t)r0 * HDIM + kb + 9];
            float a30 = Wh[(size_t)r1 * HDIM + kb + 8];
            float a31 = Wh[(size_t)r1 * HDIM + kb + 9];
            bsplit(a00, a01, ahi[c][0], alo[c][0]);
            bsplit(a10, a11, ahi[c][1], alo[c][1]);
            bsplit(a20, a21, ahi[c][2], alo[c][2]);
            bsplit(a30, a31, ahi[c][3], alo[c][3]);
        }
    }

    // cell ownership (tid<64): j = tid>>3 (0..7), b = tid&7
    const int uj = tid >> 3;
    const int ub = tid & 7;
    const int ujeven = !(uj & 1);
    const int um = uj >> 1;                // kpair index 0..3
    float creg = 0.f;

    // ---- init: zero own h slice, arrive (cell warps = warps 0,1) ----
    if (tid < 64) {
        if (ujeven) {
            g_hhi[0][(b0 + ub) * 256 + jb * 4 + um] = 0u;
            g_hlo[0][(b0 + ub) * 256 + jb * 4 + um] = 0u;
        }
        __syncwarp();
        if (lane == 0) gbar_arrive(acnt);
    }

    // prefetch x_pre for t=0 (cell threads)
    float xq[4];
    if (tid < 64) {
        #pragma unroll
        for (int q = 0; q < 4; q++)
            xq[q] = __ldg(g_xpre + ((size_t)q * HDIM + j0 + uj) * BATCH + b0 + ub);
    }

    // staging roles: kh group = 64 threads stages its 8 KB half
    const int gt  = tid & 63;
    const int sb  = gt >> 3;               // 0..7 batch row
    const int sc  = gt & 7;                // base granule
    uint32_t dstH = (uint32_t)__cvta_generic_to_shared(&slabH[sb][kh * 128 + sc * 4]);
    uint32_t dstL = (uint32_t)__cvta_generic_to_shared(&slabL[sb][kh * 128 + sc * 4]);

    for (int t = 0; t < TSTEPS; t++) {
        const int p = t & 1;

        gbar_spin(scnt, base + (unsigned long long)(t + 1) * CARRV);

        // ---- stage own kh half (4 granules per plane per thread) ----
        {
            const unsigned* srcH = &g_hhi[p][(b0 + sb) * 256 + kh * 128 + sc * 4];
            const unsigned* srcL = &g_hlo[p][(b0 + sb) * 256 + kh * 128 + sc * 4];
            #pragma unroll
            for (int i = 0; i < 4; i++) {
                cpasync16(dstH + (uint32_t)(i * 32) * 4u, srcH + i * 32);
                cpasync16(dstL + (uint32_t)(i * 32) * 4u, srcL + i * 32);
            }
            asm volatile("cp.async.commit_group;");
            asm volatile("cp.async.wait_group 0;" ::: "memory");
        }
        asm volatile("bar.sync %0, 64;" :: "r"(1 + kh) : "memory");

        // ---- MMA: 16 chunks x 3 passes ----
        float accA[4], accB[4], accC[4];
        #pragma unroll
        for (int i = 0; i < 4; i++) { accA[i] = 0.f; accB[i] = 0.f; accC[i] = 0.f; }

        #pragma unroll
        for (int c = 0; c < 16; c++) {
            int w = kh * 128 + c * 8 + t4;
            unsigned bh0 = slabH[gid][w];
            unsigned bh1 = slabH[gid][w + 4];
            unsigned bl0 = slabL[gid][w];
            unsigned bl1 = slabL[gid][w + 4];
            mma_bf16(accA, ahi[c], bh0, bh1);
            mma_bf16(accB, alo[c], bh0, bh1);
            mma_bf16(accC, ahi[c], bl0, bl1);
        }

        // ---- spill into parity buffer: rows (gid, gid+8) ----
        {
            float d0 = accA[0] + accB[0] + accC[0];
            float d1 = accA[1] + accB[1] + accC[1];
            float d2 = accA[2] + accB[2] + accC[2];
            float d3 = accA[3] + accB[3] + accC[3];
            *(float2*)&sred[p][mtp][kh][gid][2 * t4]     = make_float2(d0, d1);
            *(float2*)&sred[p][mtp][kh][gid + 8][2 * t4] = make_float2(d2, d3);
        }

        if (tid >= 64) {
            asm volatile("bar.arrive 3, 128;" ::: "memory");
            continue;
        }
        asm volatile("bar.sync 3, 128;" ::: "memory");

        // ---- cell (warps 0-1): 2-way reduce, activations, pack, arrive ----
        {
            float pre0 = xq[0] + sred[p][0][0][uj][ub]     + sred[p][0][1][uj][ub];
            float pre1 = xq[1] + sred[p][0][0][8 + uj][ub] + sred[p][0][1][8 + uj][ub];
            float pre2 = xq[2] + sred[p][1][0][uj][ub]     + sred[p][1][1][uj][ub];
            float pre3 = xq[3] + sred[p][1][0][8 + uj][ub] + sred[p][1][1][8 + uj][ub];
            float ig = fsig(pre0);
            float fg = fsig(pre1);
            float og = fsig(pre2);
            float gt = ftanh(pre3);
            creg = creg * fg + ig * gt;
            float hn = og * ftanh(creg);
            float hn1 = __shfl_down_sync(0xFFFFFFFFu, hn, 8);
            if (ujeven) {
                unsigned ph, pl;
                bsplit(hn, hn1, ph, pl);
                g_hhi[p ^ 1][(b0 + ub) * 256 + jb * 4 + um] = ph;
                g_hlo[p ^ 1][(b0 + ub) * 256 + jb * 4 + um] = pl;
            }
            __syncwarp();
            if (lane == 0) gbar_arrive(acnt);      // publish h(t+1)

            // off-critical-path work after arrive
            out[((size_t)t * BATCH + b0 + ub) * HDIM + j0 + uj] = hn;
            if (t == TSTEPS - 1) {
                size_t o2 = (size_t)TSTEPS * BATCH * HDIM;
                out[o2 + (b0 + ub) * HDIM + j0 + uj] = hn;
                out[o2 + BATCH * HDIM + (b0 + ub) * HDIM + j0 + uj] = creg;
            }
            int tn = (t + 1 < TSTEPS) ? t + 1 : t;
            #pragma unroll
            for (int q = 0; q < 4; q++)
                xq[q] = __ldg(g_xpre + ((size_t)tn * GDIM + q * HDIM + j0 + uj) * BATCH + b0 + ub);
        }
    }
}

// ============================================================
extern "C" void kernel_launch(void* const* d_in, const int* in_sizes, int n_in,
                              void* d_out, int out_size)
{
    const float* x  = (const float*)d_in[0];
    const float* Wi = (const float*)d_in[1];
    const float* bi = (const float*)d_in[2];
    const float* Wh = (const float*)d_in[3];
    const float* bh = (const float*)d_in[4];
    float* out = (float*)d_out;

    size_t p1_smem = (size_t)(4 * 128 * 36) * sizeof(unsigned); // 73728 B
    cudaFuncSetAttribute(p1_gemm, cudaFuncAttributeMaxDynamicSharedMemorySize,
                         (int)p1_smem);

    split_x<<<TOTX / 256, 256>>>(x);
    split_wi<<<TOTW / 256, 256>>>(Wi);
    dim3 g1(GDIM / 128, TSTEPS / P1T);
    p1_gemm<<<g1, 256, p1_smem>>>(bi, bh);
    lstm_rec<<<RG2, 128>>>(Wh, out);
}